// round 7
// baseline (speedup 1.0000x reference)
#include <cuda_runtime.h>
#include <cuda_fp16.h>
#include <cstdint>

#define B_     8
#define N_     4096
#define D_     1024
#define EMB_   64
#define CLN_   10
#define TILE_M 64
#define KC_    32                  // k-chunk
#define NCHUNK (D_ / KC_)          // 32
#define NTHR   128
#define NCTA_X (N_ / TILE_M)       // 64 CTAs per batch
#define PSTRIDE 656
#define NSTAGE 4

// ---------------- device scratch (allocation-free rule) ----------------
__device__ float g_part[B_ * NCTA_X * PSTRIDE];
__device__ int   g_done[B_];                      // zero-init; self-resetting
__device__ __align__(16) __half g_W1hi[EMB_ * D_];
__device__ __align__(16) __half g_W1lo[EMB_ * D_];

// ---------------- dynamic smem layout (bytes) ----------------
#define SM_B1S    0                // 64 f
#define SM_LABS   256              // 64 int
#define SM_CSUM   512              // 2 x 640 f -> ends 5632
#define SM_BBUF   6144
#define B_STAGE   8192             // hi 4KB + lo 4KB (64 rows x 64B each)
#define BLO_OFF   4096
#define SMEM_TOTAL (SM_BBUF + NSTAGE * B_STAGE)   // 38912 -> 4+ CTAs/SM

__device__ __forceinline__ uint32_t smem_u32(const void* p) {
    uint32_t a;
    asm("{ .reg .u64 t; cvta.to.shared.u64 t, %1; cvt.u32.u64 %0, t; }" : "=r"(a) : "l"(p));
    return a;
}
__device__ __forceinline__ uint32_t sw64(uint32_t o) { return o ^ ((o >> 3) & 0x30); }

__device__ __forceinline__ void ldmx4(uint32_t* r, uint32_t addr) {
    asm volatile("ldmatrix.sync.aligned.m8n8.x4.shared.b16 {%0,%1,%2,%3}, [%4];"
                 : "=r"(r[0]), "=r"(r[1]), "=r"(r[2]), "=r"(r[3]) : "r"(addr));
}
__device__ __forceinline__ void mma16816(float* c, const uint32_t* a, uint32_t b0, uint32_t b1) {
    asm volatile("mma.sync.aligned.m16n8k16.row.col.f32.f16.f16.f32 "
                 "{%0,%1,%2,%3}, {%4,%5,%6,%7}, {%8,%9}, {%0,%1,%2,%3};"
                 : "+f"(c[0]), "+f"(c[1]), "+f"(c[2]), "+f"(c[3])
                 : "r"(a[0]), "r"(a[1]), "r"(a[2]), "r"(a[3]), "r"(b0), "r"(b1));
}
__device__ __forceinline__ void cpasync16(uint32_t saddr, const void* gaddr) {
    asm volatile("cp.async.cg.shared.global [%0], [%1], 16;" :: "r"(saddr), "l"(gaddr));
}

// ---------------------------------------------------------------------------
// Kernel 0: split-convert W1 to fp16 hi/lo (vectorized)
// ---------------------------------------------------------------------------
__global__ void init_kernel(const float* __restrict__ W1) {
    int i4 = blockIdx.x * 256 + threadIdx.x;      // float4 index
    float4 v = *(const float4*)(W1 + (size_t)i4 * 4);
    __half2 h0 = __floats2half2_rn(v.x, v.y);
    __half2 h1 = __floats2half2_rn(v.z, v.w);
    float2 f0 = __half22float2(h0), f1 = __half22float2(h1);
    __half2 l0 = __floats2half2_rn(v.x - f0.x, v.y - f0.y);
    __half2 l1 = __floats2half2_rn(v.z - f1.x, v.w - f1.y);
    uint2 hv, lv;
    hv.x = *(uint32_t*)&h0; hv.y = *(uint32_t*)&h1;
    lv.x = *(uint32_t*)&l0; lv.y = *(uint32_t*)&l1;
    *(uint2*)(g_W1hi + (size_t)i4 * 4) = hv;
    *(uint2*)(g_W1lo + (size_t)i4 * 4) = lv;
}

// ---------------------------------------------------------------------------
// Fused kernel: A direct-LDG (reg double-buffer) + B 4-stage cp.async,
// 3-term fp16-split mma.sync; last CTA per batch runs the attention head.
// ---------------------------------------------------------------------------
__global__ void __launch_bounds__(NTHR)
fused_kernel(const float* __restrict__ data,
             const int*   __restrict__ labels,
             const float* __restrict__ b1,
             const float* __restrict__ Wa1, const float* __restrict__ ba1,
             const float* __restrict__ Wa2, const float* __restrict__ ba2,
             const float* __restrict__ Wf1, const float* __restrict__ bf1,
             const float* __restrict__ Wf2, const float* __restrict__ bf2,
             float* __restrict__ out) {
    extern __shared__ char smem[];
    const uint32_t sb = smem_u32(smem);
    const int tid  = threadIdx.x;
    const int warp = tid >> 5;
    const int lane = tid & 31;
    const int b    = blockIdx.y;
    const int bx   = blockIdx.x;
    const int p0   = bx * TILE_M;

    float* b1s  = (float*)(smem + SM_B1S);
    int*   labs = (int*)  (smem + SM_LABS);
    float* csum = (float*)(smem + SM_CSUM);

    if (tid < EMB_)   b1s[tid]  = b1[tid];
    if (tid < TILE_M) labs[tid] = labels[b * N_ + p0 + tid];
    for (int i = tid; i < 2 * CLN_ * EMB_; i += NTHR) csum[i] = 0.0f;

    const float* dbase = data + (size_t)(b * N_ + p0) * D_;

    // B stage fill (per-thread share: 2 rows-of-4 x 16B, hi+lo)
    const int br = tid >> 2;            // used with +32 for second half
    const int bq = tid & 3;
    auto issueB = [&](int chunk) {
        const int kc = chunk * KC_;
        const uint32_t bbase = sb + SM_BBUF + (chunk & (NSTAGE - 1)) * B_STAGE;
#pragma unroll
        for (int l = 0; l < 2; l++) {
            int r = br + l * 32;
            uint32_t sw = sw64((uint32_t)(r * 64 + bq * 16));
            cpasync16(bbase + sw,           g_W1hi + (size_t)r * D_ + kc + bq * 8);
            cpasync16(bbase + BLO_OFF + sw, g_W1lo + (size_t)r * D_ + kc + bq * 8);
        }
    };

    // A fragment source addresses (direct global LDG, mma layout)
    const int a_r = warp * 16 + (lane >> 2);
    const int a_c = 2 * (lane & 3);
    const float* arow0 = dbase + (size_t)a_r * D_ + a_c;
    const float* arow8 = arow0 + (size_t)8 * D_;

    auto loadA = [&](float2* v, int chunk) {
        const int kc = chunk * KC_;
#pragma unroll
        for (int ks = 0; ks < 2; ks++) {
            v[ks * 4 + 0] = *(const float2*)(arow0 + kc + ks * 16);
            v[ks * 4 + 1] = *(const float2*)(arow8 + kc + ks * 16);
            v[ks * 4 + 2] = *(const float2*)(arow0 + kc + ks * 16 + 8);
            v[ks * 4 + 3] = *(const float2*)(arow8 + kc + ks * 16 + 8);
        }
    };

    // ---- prologue: 3 B stages in flight, A chunk 0 in regs ----
    issueB(0); asm volatile("cp.async.commit_group;");
    issueB(1); asm volatile("cp.async.commit_group;");
    issueB(2); asm volatile("cp.async.commit_group;");
    float2 va[8], vn[8];
    loadA(va, 0);

    float acc[8][4];
#pragma unroll
    for (int nt = 0; nt < 8; nt++)
#pragma unroll
        for (int i = 0; i < 4; i++) acc[nt][i] = 0.0f;

    const uint32_t brow8 = (uint32_t)(((lane >> 4) & 1) * 8 + (lane & 7));
    const uint32_t bkb   = (uint32_t)(((lane >> 3) & 1) * 16);

    for (int c = 0; c < NCHUNK; c++) {
        asm volatile("cp.async.wait_group 2;");
        __syncthreads();                      // B(c) visible; slot (c+3)&3 free

        if (c + 3 < NCHUNK) issueB(c + 3);
        asm volatile("cp.async.commit_group;");   // uniform group count

        if (c + 1 < NCHUNK) loadA(vn, c + 1);     // LDG flies under compute

        const uint32_t bbufa = sb + SM_BBUF + (c & (NSTAGE - 1)) * B_STAGE;
#pragma unroll
        for (int ks = 0; ks < 2; ks++) {
            float2 v00 = va[ks * 4 + 0], v10 = va[ks * 4 + 1];
            float2 v01 = va[ks * 4 + 2], v11 = va[ks * 4 + 3];
            __half2 h00 = __floats2half2_rn(v00.x, v00.y);
            __half2 h10 = __floats2half2_rn(v10.x, v10.y);
            __half2 h01 = __floats2half2_rn(v01.x, v01.y);
            __half2 h11 = __floats2half2_rn(v11.x, v11.y);
            float2 f00 = __half22float2(h00), f10 = __half22float2(h10);
            float2 f01 = __half22float2(h01), f11 = __half22float2(h11);
            __half2 e00 = __floats2half2_rn(v00.x - f00.x, v00.y - f00.y);
            __half2 e10 = __floats2half2_rn(v10.x - f10.x, v10.y - f10.y);
            __half2 e01 = __floats2half2_rn(v01.x - f01.x, v01.y - f01.y);
            __half2 e11 = __floats2half2_rn(v11.x - f11.x, v11.y - f11.y);
            uint32_t ah[4] = { *(uint32_t*)&h00, *(uint32_t*)&h10,
                               *(uint32_t*)&h01, *(uint32_t*)&h11 };
            uint32_t al[4] = { *(uint32_t*)&e00, *(uint32_t*)&e10,
                               *(uint32_t*)&e01, *(uint32_t*)&e11 };
#pragma unroll
            for (int j = 0; j < 4; j++) {
                uint32_t bh[4], bl[4];
                uint32_t boff = sw64((uint32_t)(j * 16 + (int)brow8) * 64 +
                                     (uint32_t)(ks * 32) + bkb);
                ldmx4(bh, bbufa + boff);
                ldmx4(bl, bbufa + BLO_OFF + boff);
                mma16816(acc[2 * j],     ah, bh[0], bh[1]);
                mma16816(acc[2 * j],     ah, bl[0], bl[1]);
                mma16816(acc[2 * j],     al, bh[0], bh[1]);
                mma16816(acc[2 * j + 1], ah, bh[2], bh[3]);
                mma16816(acc[2 * j + 1], ah, bl[2], bl[3]);
                mma16816(acc[2 * j + 1], al, bh[2], bh[3]);
            }
        }
#pragma unroll
        for (int i = 0; i < 8; i++) va[i] = vn[i];
    }

    // ---- epilogue: bias + ReLU -> e-tile (64 x 66, reuse B buffers) ----
    float* etile = (float*)(smem + SM_BBUF);
    __syncthreads();
    {
        int r0 = warp * 16 + (lane >> 2);
        int cq = 2 * (lane & 3);
#pragma unroll
        for (int nt = 0; nt < 8; nt++) {
            int col = nt * 8 + cq;
            float bv0 = b1s[col], bv1 = b1s[col + 1];
            etile[r0 * 66 + col]           = fmaxf(acc[nt][0] + bv0, 0.0f);
            etile[r0 * 66 + col + 1]       = fmaxf(acc[nt][1] + bv1, 0.0f);
            etile[(r0 + 8) * 66 + col]     = fmaxf(acc[nt][2] + bv0, 0.0f);
            etile[(r0 + 8) * 66 + col + 1] = fmaxf(acc[nt][3] + bv1, 0.0f);
        }
    }
    __syncthreads();

    {   // split-row segment reduction: no atomics
        int half = tid >> 6;
        int e    = tid & 63;
        float* cs = csum + half * (CLN_ * EMB_);
        int rbase = half * 32;
        for (int r = 0; r < 32; r++) {
            int row = rbase + r;
            cs[labs[row] * EMB_ + e] += etile[row * 66 + e];
        }
    }
    __syncthreads();

    float* prow = g_part + ((size_t)b * NCTA_X + bx) * PSTRIDE;
    for (int i = tid; i < CLN_ * EMB_; i += NTHR)
        prow[i] = csum[i] + csum[CLN_ * EMB_ + i];
    if (tid < CLN_) {
        int cnt = 0;
        for (int r = 0; r < TILE_M; r++) cnt += (labs[r] == tid);
        prow[640 + tid] = (float)cnt;
    }
    __threadfence();
    __syncthreads();

    // ---- last CTA of this batch runs the head ----
    __shared__ int s_last;
    if (tid == 0) s_last = (atomicAdd(&g_done[b], 1) == NCTA_X - 1) ? 1 : 0;
    __syncthreads();
    if (!s_last) return;
    __threadfence();

    float* hc    = (float*)(smem + SM_BBUF);        // reuse B region
    float* h     = hc + 656;
    float* u     = h + 640;
    float* score = u + 320;
    float* Avec  = score + 16;
    float* mask  = Avec + 16;
    float* Mv    = mask + 16;
    float* f     = Mv + 64;

    for (int i = tid; i < 650; i += NTHR) {
        float s = 0.0f;
        const float* base = g_part + (size_t)b * NCTA_X * PSTRIDE + i;
#pragma unroll
        for (int j = 0; j < NCTA_X; j++) s += base[j * PSTRIDE];
        hc[i] = s;
    }
    __syncthreads();

    if (tid < EMB_) {
        for (int c = 0; c < CLN_; c++)
            h[c * EMB_ + tid] = hc[c * EMB_ + tid] / fmaxf(hc[640 + c], 1.0f);
    }
    if (tid < CLN_) mask[tid] = (hc[640 + tid] > 0.0f) ? 1.0f : 0.0f;
    __syncthreads();

    if (tid < 32) {
        for (int c = 0; c < CLN_; c++) {
            float s = ba1[tid];
            for (int e = 0; e < EMB_; e++) s += h[c * EMB_ + e] * Wa1[tid * EMB_ + e];
            u[c * 32 + tid] = tanhf(s);
        }
    }
    __syncthreads();

    if (tid < CLN_) {
        float s = ba2[0];
        for (int k = 0; k < 32; k++) s += u[tid * 32 + k] * Wa2[k];
        score[tid] = s;
    }
    __syncthreads();

    if (tid == 0) {
        float xmax = -1e30f;
        for (int c = 0; c < CLN_; c++) {
            float xm = score[c] * mask[c] + (1.0f - 1.0f / (mask[c] + 1e-5f));
            xmax = fmaxf(xmax, xm);
        }
        float ssum = 0.0f;
        for (int c = 0; c < CLN_; c++) {
            float ex = expf(score[c] - xmax) * mask[c];
            Avec[c] = ex;
            ssum += ex;
        }
        for (int c = 0; c < CLN_; c++) Avec[c] /= ssum;
    }
    __syncthreads();

    if (tid < EMB_) {
        float m = 0.0f;
        for (int c = 0; c < CLN_; c++) m += Avec[c] * h[c * EMB_ + tid];
        Mv[tid] = m;
    }
    __syncthreads();

    if (tid < 32) {
        float s = bf1[tid];
        for (int e = 0; e < EMB_; e++) s += Mv[e] * Wf1[tid * EMB_ + e];
        f[tid] = fmaxf(s, 0.0f);
    }
    __syncthreads();

    if (tid == 0) {
        float s = bf2[0];
        for (int k = 0; k < 32; k++) s += f[k] * Wf2[k];
        out[b] = s;
        g_done[b] = 0;      // reset for next graph replay
    }
}

// ---------------------------------------------------------------------------
extern "C" void kernel_launch(void* const* d_in, const int* in_sizes, int n_in,
                              void* d_out, int out_size) {
    const float* data   = (const float*)d_in[0];
    const int*   labels = (const int*)  d_in[1];
    const float* W1     = (const float*)d_in[2];
    const float* b1     = (const float*)d_in[3];
    const float* Wa1    = (const float*)d_in[4];
    const float* ba1    = (const float*)d_in[5];
    const float* Wa2    = (const float*)d_in[6];
    const float* ba2    = (const float*)d_in[7];
    const float* Wf1    = (const float*)d_in[8];
    const float* bf1    = (const float*)d_in[9];
    const float* Wf2    = (const float*)d_in[10];
    const float* bf2    = (const float*)d_in[11];

    cudaFuncSetAttribute(fused_kernel, cudaFuncAttributeMaxDynamicSharedMemorySize,
                         SMEM_TOTAL);

    init_kernel<<<64, 256>>>(W1);
    fused_kernel<<<dim3(NCTA_X, B_), NTHR, SMEM_TOTAL>>>(
        data, labels, b1, Wa1, ba1, Wa2, ba2, Wf1, bf1, Wf2, bf2,
        (float*)d_out);
}